// round 1
// baseline (speedup 1.0000x reference)
#include <cuda_runtime.h>
#include <math.h>

// ---------------- problem constants ----------------
#define BATCH   4
#define LSEQ    2305          // 1 global token + 48*48
#define DM      256           // D_MODEL
#define DI      512           // D_INNER
#define DS      16            // D_STATE
#define DTR     16            // DT_RANK
#define NDBL    48            // DTR + 2*DS
#define MROWS   (BATCH*LSEQ)  // 9220
#define CHUNK   128
#define NCHUNK  19            // ceil(2305/128)

// ---------------- scratch (device globals; no allocation allowed) ----------------
__device__ float g_seq [MROWS*DM];            //  9.4 MB
__device__ float g_xz  [MROWS*2*DI];          // 37.8 MB  (u | z)
__device__ float g_u   [MROWS*DI];            // 18.9 MB  (post conv+silu)
__device__ float g_xdbl[MROWS*NDBL];          //  1.8 MB  (dt_raw | B | C)
__device__ float g_dt  [MROWS*DI];            // 18.9 MB
__device__ float g_y   [MROWS*DI];            // 18.9 MB  (final gated y)
__device__ float g_P   [BATCH*DI*NCHUNK*DS];  //  2.5 MB
__device__ float g_hf  [BATCH*DI*NCHUNK*DS];
__device__ float g_hin [BATCH*DI*NCHUNK*DS];

// ---------------- small math helpers ----------------
__device__ __forceinline__ float siluf(float x) {
    return x / (1.0f + __expf(-x));
}
__device__ __forceinline__ float softplusf(float x) {
    // numerically stable: max(x,0) + log1p(exp(-|x|))
    return fmaxf(x, 0.0f) + log1pf(__expf(-fabsf(x)));
}

// ---------------- 1) build seq: pixel_shuffle + transpose + prepend token ----------------
__global__ void build_seq_kernel(const float* __restrict__ x,
                                 const float* __restrict__ gtok) {
    int idx = blockIdx.x * blockDim.x + threadIdx.x;
    if (idx >= MROWS * DM) return;
    int c = idx % DM;
    int l = (idx / DM) % LSEQ;
    int b = idx / (DM * LSEQ);
    float v;
    if (l == 0) {
        v = gtok[c];
    } else {
        int lp = l - 1;
        int H2 = lp / 48, W2 = lp % 48;
        int r1 = H2 & 1, h = H2 >> 1;
        int r2 = W2 & 1, w = W2 >> 1;
        int ch = c * 4 + r1 * 2 + r2;
        v = x[((b * 1024 + ch) * 24 + h) * 24 + w];
    }
    g_seq[idx] = v;
}

// ---------------- 2) SGEMM  C[M,N] = A[M,K] * W[N,K]^T ----------------
// 128x128 tile, BK=8, 256 threads, 8x8 per thread. FUSE_OUT fuses the final
// pixel_unshuffle write (skips the l==0 token row).
template<bool FUSE_OUT>
__global__ __launch_bounds__(256)
void sgemm_kernel(const float* __restrict__ A, const float* __restrict__ W,
                  float* __restrict__ C, int M, int N, int K) {
    __shared__ __align__(16) float As[8][128];
    __shared__ __align__(16) float Bs[8][128];
    const int tid = threadIdx.x;
    const int m0 = blockIdx.x * 128;
    const int n0 = blockIdx.y * 128;
    const int tx = tid & 15;         // 0..15 -> cols
    const int ty = tid >> 4;         // 0..15 -> rows
    const int lr = tid >> 1;         // 0..127
    const int lc = (tid & 1) * 4;    // 0 or 4

    float acc[8][8];
#pragma unroll
    for (int i = 0; i < 8; i++)
#pragma unroll
        for (int j = 0; j < 8; j++) acc[i][j] = 0.0f;

    for (int k0 = 0; k0 < K; k0 += 8) {
        float4 av = make_float4(0.f, 0.f, 0.f, 0.f);
        if (m0 + lr < M)
            av = *reinterpret_cast<const float4*>(&A[(size_t)(m0 + lr) * K + k0 + lc]);
        As[lc + 0][lr] = av.x; As[lc + 1][lr] = av.y;
        As[lc + 2][lr] = av.z; As[lc + 3][lr] = av.w;

        float4 wv = make_float4(0.f, 0.f, 0.f, 0.f);
        if (n0 + lr < N)
            wv = *reinterpret_cast<const float4*>(&W[(size_t)(n0 + lr) * K + k0 + lc]);
        Bs[lc + 0][lr] = wv.x; Bs[lc + 1][lr] = wv.y;
        Bs[lc + 2][lr] = wv.z; Bs[lc + 3][lr] = wv.w;

        __syncthreads();
#pragma unroll
        for (int kk = 0; kk < 8; kk++) {
            float4 a0 = *reinterpret_cast<const float4*>(&As[kk][ty * 8]);
            float4 a1 = *reinterpret_cast<const float4*>(&As[kk][ty * 8 + 4]);
            float4 b0 = *reinterpret_cast<const float4*>(&Bs[kk][tx * 8]);
            float4 b1 = *reinterpret_cast<const float4*>(&Bs[kk][tx * 8 + 4]);
            float ar[8] = {a0.x, a0.y, a0.z, a0.w, a1.x, a1.y, a1.z, a1.w};
            float br[8] = {b0.x, b0.y, b0.z, b0.w, b1.x, b1.y, b1.z, b1.w};
#pragma unroll
            for (int i = 0; i < 8; i++)
#pragma unroll
                for (int j = 0; j < 8; j++) acc[i][j] = fmaf(ar[i], br[j], acc[i][j]);
        }
        __syncthreads();
    }

#pragma unroll
    for (int i = 0; i < 8; i++) {
        int m = m0 + ty * 8 + i;
        if (m >= M) continue;
#pragma unroll
        for (int j = 0; j < 8; j++) {
            int n = n0 + tx * 8 + j;
            if (n >= N) continue;
            if (!FUSE_OUT) {
                C[(size_t)m * N + n] = acc[i][j];
            } else {
                int b = m / LSEQ, l = m % LSEQ;
                if (l > 0) {
                    int lp = l - 1;
                    int H2 = lp / 48, W2 = lp % 48;
                    int ch = n * 4 + (H2 & 1) * 2 + (W2 & 1);
                    C[((b * 1024 + ch) * 24 + (H2 >> 1)) * 24 + (W2 >> 1)] = acc[i][j];
                }
            }
        }
    }
}

// ---------------- 3) causal depthwise conv (k=4) + bias + silu ----------------
__global__ void conv_kernel(const float* __restrict__ conv_w,
                            const float* __restrict__ conv_b) {
    int idx = blockIdx.x * blockDim.x + threadIdx.x;
    if (idx >= MROWS * DI) return;
    int d = idx % DI;
    int l = (idx / DI) % LSEQ;
    int b = idx / (DI * LSEQ);
    float acc = conv_b[d];
#pragma unroll
    for (int k = 0; k < 4; k++) {
        int ls = l - 3 + k;
        if (ls >= 0)
            acc = fmaf(g_xz[((size_t)(b * LSEQ + ls)) * (2 * DI) + d], conv_w[d * 4 + k], acc);
    }
    g_u[(size_t)(b * LSEQ + l) * DI + d] = siluf(acc);
}

// ---------------- 4) dt = softplus(xdbl[:, :16] @ dt_proj_w^T + b) ----------------
__global__ void dt_kernel(const float* __restrict__ Wdt,
                          const float* __restrict__ bdt) {
    int m = blockIdx.x;       // row
    int d = threadIdx.x;      // 0..511
    __shared__ float r[DTR];
    if (d < DTR) r[d] = g_xdbl[(size_t)m * NDBL + d];
    __syncthreads();
    float acc = bdt[d];
#pragma unroll
    for (int k = 0; k < DTR; k++) acc = fmaf(r[k], Wdt[d * DTR + k], acc);
    g_dt[(size_t)m * DI + d] = softplusf(acc);
}

// ---------------- 5) scan pass 1: per-chunk products + local finals ----------------
__global__ void scan_pass1_kernel(const float* __restrict__ A_log) {
    int d = blockIdx.x * 128 + threadIdx.x;
    int c = blockIdx.y;
    int b = blockIdx.z;
    float Aa[DS], h[DS], P[DS];
#pragma unroll
    for (int n = 0; n < DS; n++) {
        Aa[n] = -__expf(A_log[d * DS + n]);
        h[n] = 0.0f; P[n] = 1.0f;
    }
    int l0 = c * CHUNK;
    int l1 = min(LSEQ, l0 + CHUNK);
    for (int l = l0; l < l1; l++) {
        size_t row = (size_t)b * LSEQ + l;
        float dtv = g_dt[row * DI + d];
        float uv  = g_u [row * DI + d];
        float du  = dtv * uv;
        const float4* Bp = reinterpret_cast<const float4*>(&g_xdbl[row * NDBL + DTR]);
        float4 t0 = Bp[0], t1 = Bp[1], t2 = Bp[2], t3 = Bp[3];
        float Bv[DS] = {t0.x, t0.y, t0.z, t0.w, t1.x, t1.y, t1.z, t1.w,
                        t2.x, t2.y, t2.z, t2.w, t3.x, t3.y, t3.z, t3.w};
#pragma unroll
        for (int n = 0; n < DS; n++) {
            float dA = __expf(dtv * Aa[n]);
            P[n] *= dA;
            h[n] = fmaf(dA, h[n], du * Bv[n]);
        }
    }
    size_t base = (((size_t)b * DI + d) * NCHUNK + c) * DS;
#pragma unroll
    for (int n = 0; n < DS; n++) { g_P[base + n] = P[n]; g_hf[base + n] = h[n]; }
}

// ---------------- 6) sequential combine across chunks ----------------
__global__ void scan_combine_kernel() {
    int idx = blockIdx.x * blockDim.x + threadIdx.x;
    if (idx >= BATCH * DI * DS) return;
    int n = idx % DS;
    int d = (idx / DS) % DI;
    int b = idx / (DS * DI);
    float h = 0.0f;
    for (int c = 0; c < NCHUNK; c++) {
        size_t base = (((size_t)b * DI + d) * NCHUNK + c) * DS + n;
        g_hin[base] = h;
        h = fmaf(g_P[base], h, g_hf[base]);
    }
}

// ---------------- 7) scan pass 2: rescan with correct h0, fused epilogue ----------------
__global__ void scan_pass2_kernel(const float* __restrict__ A_log,
                                  const float* __restrict__ Dp) {
    int d = blockIdx.x * 128 + threadIdx.x;
    int c = blockIdx.y;
    int b = blockIdx.z;
    float Aa[DS], h[DS];
    size_t hbase = (((size_t)b * DI + d) * NCHUNK + c) * DS;
#pragma unroll
    for (int n = 0; n < DS; n++) {
        Aa[n] = -__expf(A_log[d * DS + n]);
        h[n] = g_hin[hbase + n];
    }
    float Dd = Dp[d];
    int l0 = c * CHUNK;
    int l1 = min(LSEQ, l0 + CHUNK);
    for (int l = l0; l < l1; l++) {
        size_t row = (size_t)b * LSEQ + l;
        float dtv = g_dt[row * DI + d];
        float uv  = g_u [row * DI + d];
        float du  = dtv * uv;
        const float4* BCp = reinterpret_cast<const float4*>(&g_xdbl[row * NDBL + DTR]);
        float4 t0 = BCp[0], t1 = BCp[1], t2 = BCp[2], t3 = BCp[3];
        float4 t4 = BCp[4], t5 = BCp[5], t6 = BCp[6], t7 = BCp[7];
        float Bv[DS] = {t0.x, t0.y, t0.z, t0.w, t1.x, t1.y, t1.z, t1.w,
                        t2.x, t2.y, t2.z, t2.w, t3.x, t3.y, t3.z, t3.w};
        float Cv[DS] = {t4.x, t4.y, t4.z, t4.w, t5.x, t5.y, t5.z, t5.w,
                        t6.x, t6.y, t6.z, t6.w, t7.x, t7.y, t7.z, t7.w};
        float y = 0.0f;
#pragma unroll
        for (int n = 0; n < DS; n++) {
            float dA = __expf(dtv * Aa[n]);
            h[n] = fmaf(dA, h[n], du * Bv[n]);
            y = fmaf(h[n], Cv[n], y);
        }
        float z = g_xz[row * (2 * DI) + DI + d];
        g_y[row * DI + d] = (y + uv * Dd) * siluf(z);
    }
}

// ---------------- launch ----------------
extern "C" void kernel_launch(void* const* d_in, const int* in_sizes, int n_in,
                              void* d_out, int out_size) {
    const float* x          = (const float*)d_in[0];
    const float* gtok       = (const float*)d_in[1];
    const float* in_proj_w  = (const float*)d_in[2];
    const float* conv_w     = (const float*)d_in[3];
    const float* conv_b     = (const float*)d_in[4];
    const float* x_proj_w   = (const float*)d_in[5];
    const float* dt_proj_w  = (const float*)d_in[6];
    const float* dt_proj_b  = (const float*)d_in[7];
    const float* A_log      = (const float*)d_in[8];
    const float* Dp         = (const float*)d_in[9];
    const float* out_proj_w = (const float*)d_in[10];
    float* out = (float*)d_out;

    float *p_seq, *p_xz, *p_u, *p_xdbl, *p_y;
    cudaGetSymbolAddress((void**)&p_seq,  g_seq);
    cudaGetSymbolAddress((void**)&p_xz,   g_xz);
    cudaGetSymbolAddress((void**)&p_u,    g_u);
    cudaGetSymbolAddress((void**)&p_xdbl, g_xdbl);
    cudaGetSymbolAddress((void**)&p_y,    g_y);

    // 1. seq = [token; pixel_shuffle(x)]
    build_seq_kernel<<<(MROWS * DM + 255) / 256, 256>>>(x, gtok);

    // 2. xz = seq @ in_proj_w^T   (M=9220, N=1024, K=256)
    {
        dim3 grid((MROWS + 127) / 128, (2 * DI + 127) / 128);
        sgemm_kernel<false><<<grid, 256>>>(p_seq, in_proj_w, p_xz, MROWS, 2 * DI, DM);
    }

    // 3. u = silu(causal_conv(xz[:, :512]) + b)
    conv_kernel<<<(MROWS * DI + 255) / 256, 256>>>(conv_w, conv_b);

    // 4. x_dbl = u @ x_proj_w^T   (N=48, K=512)
    {
        dim3 grid((MROWS + 127) / 128, 1);
        sgemm_kernel<false><<<grid, 256>>>(p_u, x_proj_w, p_xdbl, MROWS, NDBL, DI);
    }

    // 5. dt = softplus(x_dbl[:, :16] @ dt_proj_w^T + dt_proj_b)
    dt_kernel<<<MROWS, DI>>>(dt_proj_w, dt_proj_b);

    // 6-8. chunked selective scan + fused gating epilogue
    {
        dim3 grid(DI / 128, NCHUNK, BATCH);
        scan_pass1_kernel<<<grid, 128>>>(A_log);
        scan_combine_kernel<<<(BATCH * DI * DS + 255) / 256, 256>>>();
        scan_pass2_kernel<<<grid, 128>>>(A_log, Dp);
    }

    // 9. out = y @ out_proj_w^T, fused pixel_unshuffle write (N=256, K=512)
    {
        dim3 grid((MROWS + 127) / 128, (DM + 127) / 128);
        sgemm_kernel<true><<<grid, 256>>>(p_y, out_proj_w, out, MROWS, DM, DI);
    }
}

// round 4
// speedup vs baseline: 1.4813x; 1.4813x over previous
#include <cuda_runtime.h>
#include <math.h>

// ---------------- problem constants ----------------
#define BATCH   4
#define LSEQ    2305          // 1 global token + 48*48
#define DM      256           // D_MODEL
#define DI      512           // D_INNER
#define DS      16            // D_STATE
#define DTR     16            // DT_RANK
#define NDBL    48            // DTR + 2*DS
#define MROWS   (BATCH*LSEQ)  // 9220
#define CHUNK   128
#define NCHUNK  19            // ceil(2305/128)

// ---------------- scratch (device globals; no allocation allowed) ----------------
__device__ float g_seq [MROWS*DM];
__device__ float g_xz  [MROWS*2*DI];
__device__ float g_u   [MROWS*DI];
__device__ float g_xdbl[MROWS*NDBL];
__device__ float g_dt  [MROWS*DI];
__device__ float g_y   [MROWS*DI];
__device__ float g_P   [BATCH*DI*NCHUNK*DS];
__device__ float g_hf  [BATCH*DI*NCHUNK*DS];
__device__ float g_hin [BATCH*DI*NCHUNK*DS];

// ---------------- small math helpers ----------------
__device__ __forceinline__ float siluf(float x) {
    return x / (1.0f + __expf(-x));
}
__device__ __forceinline__ float softplusf(float x) {
    return fmaxf(x, 0.0f) + log1pf(__expf(-fabsf(x)));
}

// packed fp32x2 helpers (sm_100+ FFMA2 path)
__device__ __forceinline__ unsigned long long pack2(float lo, float hi) {
    unsigned long long r;
    asm("mov.b64 %0, {%1, %2};" : "=l"(r) : "f"(lo), "f"(hi));
    return r;
}
__device__ __forceinline__ void unpack2(unsigned long long v, float& lo, float& hi) {
    asm("mov.b64 {%0, %1}, %2;" : "=f"(lo), "=f"(hi) : "l"(v));
}
__device__ __forceinline__ unsigned long long ffma2(unsigned long long a,
                                                    unsigned long long b,
                                                    unsigned long long c) {
    unsigned long long d;
    asm("fma.rn.f32x2 %0, %1, %2, %3;" : "=l"(d) : "l"(a), "l"(b), "l"(c));
    return d;
}

// ---------------- 1) build seq: pixel_shuffle + transpose + prepend token ----------------
__global__ void build_seq_kernel(const float* __restrict__ x,
                                 const float* __restrict__ gtok) {
    int idx = blockIdx.x * blockDim.x + threadIdx.x;
    if (idx >= MROWS * DM) return;
    int c = idx % DM;
    int l = (idx / DM) % LSEQ;
    int b = idx / (DM * LSEQ);
    float v;
    if (l == 0) {
        v = gtok[c];
    } else {
        int lp = l - 1;
        int H2 = lp / 48, W2 = lp % 48;
        int r1 = H2 & 1, h = H2 >> 1;
        int r2 = W2 & 1, w = W2 >> 1;
        int ch = c * 4 + r1 * 2 + r2;
        v = x[((b * 1024 + ch) * 24 + h) * 24 + w];
    }
    g_seq[idx] = v;
}

// ---------------- 2) SGEMM  C[M,N] = A[M,K] * W[N,K]^T  (FFMA2 inner) ----------------
// 128x128 tile, BK=16, 256 threads, 8x8 per thread packed as 8x4 f32x2.
template<bool FUSE_OUT>
__global__ __launch_bounds__(256, 2)
void sgemm_kernel(const float* __restrict__ A, const float* __restrict__ W,
                  float* __restrict__ C, int M, int N, int K) {
    __shared__ __align__(16) float As[16][128];
    __shared__ __align__(16) float Bs[16][128];
    const int tid = threadIdx.x;
    const int m0 = blockIdx.x * 128;
    const int n0 = blockIdx.y * 128;
    const int tx = tid & 15;
    const int ty = tid >> 4;
    const int lr = tid >> 1;         // 0..127 (tile row)
    const int lc = (tid & 1) * 8;    // 0 or 8 (k offset)

    unsigned long long acc2[8][4];
#pragma unroll
    for (int i = 0; i < 8; i++)
#pragma unroll
        for (int j = 0; j < 4; j++) acc2[i][j] = 0ull;

    for (int k0 = 0; k0 < K; k0 += 16) {
        float4 a0 = make_float4(0.f,0.f,0.f,0.f), a1 = a0;
        if (m0 + lr < M) {
            const float* ap = &A[(size_t)(m0 + lr) * K + k0 + lc];
            a0 = *reinterpret_cast<const float4*>(ap);
            a1 = *reinterpret_cast<const float4*>(ap + 4);
        }
        As[lc+0][lr]=a0.x; As[lc+1][lr]=a0.y; As[lc+2][lr]=a0.z; As[lc+3][lr]=a0.w;
        As[lc+4][lr]=a1.x; As[lc+5][lr]=a1.y; As[lc+6][lr]=a1.z; As[lc+7][lr]=a1.w;

        float4 w0 = make_float4(0.f,0.f,0.f,0.f), w1 = w0;
        if (n0 + lr < N) {
            const float* wp = &W[(size_t)(n0 + lr) * K + k0 + lc];
            w0 = *reinterpret_cast<const float4*>(wp);
            w1 = *reinterpret_cast<const float4*>(wp + 4);
        }
        Bs[lc+0][lr]=w0.x; Bs[lc+1][lr]=w0.y; Bs[lc+2][lr]=w0.z; Bs[lc+3][lr]=w0.w;
        Bs[lc+4][lr]=w1.x; Bs[lc+5][lr]=w1.y; Bs[lc+6][lr]=w1.z; Bs[lc+7][lr]=w1.w;

        __syncthreads();
#pragma unroll
        for (int kk = 0; kk < 16; kk++) {
            float4 av0 = *reinterpret_cast<const float4*>(&As[kk][ty * 8]);
            float4 av1 = *reinterpret_cast<const float4*>(&As[kk][ty * 8 + 4]);
            const ulonglong2* bp = reinterpret_cast<const ulonglong2*>(&Bs[kk][tx * 8]);
            ulonglong2 bv0 = bp[0], bv1 = bp[1];
            unsigned long long br[4] = {bv0.x, bv0.y, bv1.x, bv1.y};
            float ar[8] = {av0.x, av0.y, av0.z, av0.w, av1.x, av1.y, av1.z, av1.w};
#pragma unroll
            for (int i = 0; i < 8; i++) {
                unsigned long long pa = pack2(ar[i], ar[i]);
#pragma unroll
                for (int j = 0; j < 4; j++)
                    acc2[i][j] = ffma2(pa, br[j], acc2[i][j]);
            }
        }
        __syncthreads();
    }

#pragma unroll
    for (int i = 0; i < 8; i++) {
        int m = m0 + ty * 8 + i;
        if (m >= M) continue;
        float cr[8];
#pragma unroll
        for (int j = 0; j < 4; j++) unpack2(acc2[i][j], cr[2*j], cr[2*j+1]);
#pragma unroll
        for (int j = 0; j < 8; j++) {
            int n = n0 + tx * 8 + j;
            if (n >= N) continue;
            if (!FUSE_OUT) {
                C[(size_t)m * N + n] = cr[j];
            } else {
                int b = m / LSEQ, l = m % LSEQ;
                if (l > 0) {
                    int lp = l - 1;
                    int H2 = lp / 48, W2 = lp % 48;
                    int ch = n * 4 + (H2 & 1) * 2 + (W2 & 1);
                    C[((b * 1024 + ch) * 24 + (H2 >> 1)) * 24 + (W2 >> 1)] = cr[j];
                }
            }
        }
    }
}

// ---------------- 3) causal depthwise conv (k=4) + bias + silu ----------------
__global__ void conv_kernel(const float* __restrict__ conv_w,
                            const float* __restrict__ conv_b) {
    int idx = blockIdx.x * blockDim.x + threadIdx.x;
    if (idx >= MROWS * DI) return;
    int d = idx % DI;
    int l = (idx / DI) % LSEQ;
    int b = idx / (DI * LSEQ);
    float acc = conv_b[d];
#pragma unroll
    for (int k = 0; k < 4; k++) {
        int ls = l - 3 + k;
        if (ls >= 0)
            acc = fmaf(g_xz[((size_t)(b * LSEQ + ls)) * (2 * DI) + d], conv_w[d * 4 + k], acc);
    }
    g_u[(size_t)(b * LSEQ + l) * DI + d] = siluf(acc);
}

// ---------------- 4) fused x_proj (N=48) + dt projection + softplus ----------------
// Each CTA: 64 rows. Phase A: x_dbl[64][48] = u_tile @ x_proj_w^T (BK=32).
// Phase B: dt[64][512] = softplus(x_dbl[:, :16] @ dt_proj_w^T + b).
__global__ __launch_bounds__(256)
void xproj_dt_kernel(const float* __restrict__ xw,
                     const float* __restrict__ Wdt,
                     const float* __restrict__ bdt) {
    __shared__ union {
        struct { float As[32][64]; float Ws[32][48]; } p1;   // 8KB + 6KB
        struct { float xs[64][48]; float wdt[16][512]; } p2; // 12KB + 32KB
    } sm;
    const int tid = threadIdx.x;
    const int m0 = blockIdx.x * 64;
    const int tr = tid >> 4;   // 0..15 -> 4-row group
    const int tc = tid & 15;   // 0..15 -> 3-col group

    float acc[4][3];
#pragma unroll
    for (int i = 0; i < 4; i++)
#pragma unroll
        for (int j = 0; j < 3; j++) acc[i][j] = 0.0f;

    for (int step = 0; step < 16; step++) {
        int k0 = step * 32;
        // load A tile (64x32) transposed -> As[k][m]
#pragma unroll
        for (int q = 0; q < 2; q++) {
            int f = tid * 2 + q;          // 0..511 float4 index
            int row = f >> 3;             // 0..63
            int c4 = (f & 7) * 4;         // k within tile
            float4 v = make_float4(0.f,0.f,0.f,0.f);
            if (m0 + row < MROWS)
                v = *reinterpret_cast<const float4*>(&g_u[(size_t)(m0 + row) * DI + k0 + c4]);
            sm.p1.As[c4+0][row]=v.x; sm.p1.As[c4+1][row]=v.y;
            sm.p1.As[c4+2][row]=v.z; sm.p1.As[c4+3][row]=v.w;
        }
        // load W tile (48x32) transposed -> Ws[k][n]
        for (int t = tid; t < 384; t += 256) {
            int n = t >> 3;
            int c4 = (t & 7) * 4;
            float4 v = *reinterpret_cast<const float4*>(&xw[(size_t)n * DI + k0 + c4]);
            sm.p1.Ws[c4+0][n]=v.x; sm.p1.Ws[c4+1][n]=v.y;
            sm.p1.Ws[c4+2][n]=v.z; sm.p1.Ws[c4+3][n]=v.w;
        }
        __syncthreads();
#pragma unroll
        for (int k = 0; k < 32; k++) {
            float4 a = *reinterpret_cast<const float4*>(&sm.p1.As[k][tr * 4]);
            float ar[4] = {a.x, a.y, a.z, a.w};
            float b0 = sm.p1.Ws[k][tc*3+0];
            float b1 = sm.p1.Ws[k][tc*3+1];
            float b2 = sm.p1.Ws[k][tc*3+2];
#pragma unroll
            for (int i = 0; i < 4; i++) {
                acc[i][0] = fmaf(ar[i], b0, acc[i][0]);
                acc[i][1] = fmaf(ar[i], b1, acc[i][1]);
                acc[i][2] = fmaf(ar[i], b2, acc[i][2]);
            }
        }
        __syncthreads();
    }

    // epilogue phase A: write x_dbl to global and to smem xs (union switch)
    // (sync above guarantees As/Ws reads done)
#pragma unroll
    for (int i = 0; i < 4; i++) {
        int m = m0 + tr * 4 + i;
#pragma unroll
        for (int j = 0; j < 3; j++) {
            int n = tc * 3 + j;
            sm.p2.xs[tr * 4 + i][n] = acc[i][j];
            if (m < MROWS) g_xdbl[(size_t)m * NDBL + n] = acc[i][j];
        }
    }
    // load dt_proj_w transposed -> wdt[k][d]
    for (int t = tid; t < DI * DTR; t += 256) {
        int d = t >> 4, k = t & 15;
        sm.p2.wdt[k][d] = Wdt[t];
    }
    __syncthreads();

    // phase B: each thread owns 2 d-channels, loops over 64 rows
    const int d0 = tid * 2;
    float wr0[16], wr1[16];
#pragma unroll
    for (int k = 0; k < 16; k++) { wr0[k] = sm.p2.wdt[k][d0]; wr1[k] = sm.p2.wdt[k][d0+1]; }
    const float b0 = bdt[d0], b1 = bdt[d0+1];
    for (int row = 0; row < 64; row++) {
        int m = m0 + row;
        if (m >= MROWS) break;
        float a0 = b0, a1 = b1;
#pragma unroll
        for (int k = 0; k < 16; k++) {
            float xv = sm.p2.xs[row][k];
            a0 = fmaf(xv, wr0[k], a0);
            a1 = fmaf(xv, wr1[k], a1);
        }
        float2 o = make_float2(softplusf(a0), softplusf(a1));
        *reinterpret_cast<float2*>(&g_dt[(size_t)m * DI + d0]) = o;
    }
}

// ---------------- power-chain dA helper ----------------
// If A[d,:] == a1*(1..16) (true for A_log=log(arange(1..16))), all 16
// exponentials are powers of e1=exp(dt*a1): one MUFU + squaring tree.
__device__ __forceinline__ void da_powers(float e1, float dA[DS]) {
    float e2 = e1 * e1;
    float e4 = e2 * e2;
    float e8 = e4 * e4;
    dA[0]=e1;        dA[1]=e2;        dA[2]=e2*e1;     dA[3]=e4;
    dA[4]=e4*e1;     dA[5]=e4*e2;     dA[6]=e4*e2*e1;  dA[7]=e8;
    dA[8]=e8*e1;     dA[9]=e8*e2;     dA[10]=e8*e2*e1; dA[11]=e8*e4;
    dA[12]=e8*e4*e1; dA[13]=e8*e4*e2; dA[14]=e8*e4*e2*e1; dA[15]=e8*e8;
}

// ---------------- 5) scan pass 1: per-chunk products + local finals ----------------
__global__ void scan_pass1_kernel(const float* __restrict__ A_log) {
    int d = blockIdx.x * 128 + threadIdx.x;
    int c = blockIdx.y;
    int b = blockIdx.z;
    float Aa[DS], h[DS], P[DS];
    bool chain = true;
#pragma unroll
    for (int n = 0; n < DS; n++) {
        Aa[n] = -__expf(A_log[d * DS + n]);
        h[n] = 0.0f; P[n] = 1.0f;
    }
    float a1 = Aa[0];
#pragma unroll
    for (int n = 0; n < DS; n++)
        chain = chain && (fabsf(Aa[n] - a1 * (n + 1)) < 1e-3f * (n + 1));

    int l0 = c * CHUNK;
    int l1 = min(LSEQ, l0 + CHUNK);
    for (int l = l0; l < l1; l++) {
        size_t row = (size_t)b * LSEQ + l;
        float dtv = g_dt[row * DI + d];
        float uv  = g_u [row * DI + d];
        float du  = dtv * uv;
        const float4* Bp = reinterpret_cast<const float4*>(&g_xdbl[row * NDBL + DTR]);
        float4 t0 = Bp[0], t1 = Bp[1], t2 = Bp[2], t3 = Bp[3];
        float Bv[DS] = {t0.x, t0.y, t0.z, t0.w, t1.x, t1.y, t1.z, t1.w,
                        t2.x, t2.y, t2.z, t2.w, t3.x, t3.y, t3.z, t3.w};
        float dA[DS];
        if (chain) {
            da_powers(__expf(dtv * a1), dA);
        } else {
#pragma unroll
            for (int n = 0; n < DS; n++) dA[n] = __expf(dtv * Aa[n]);
        }
#pragma unroll
        for (int n = 0; n < DS; n++) {
            P[n] *= dA[n];
            h[n] = fmaf(dA[n], h[n], du * Bv[n]);
        }
    }
    size_t base = (((size_t)b * DI + d) * NCHUNK + c) * DS;
#pragma unroll
    for (int n = 0; n < DS; n++) { g_P[base + n] = P[n]; g_hf[base + n] = h[n]; }
}

// ---------------- 6) sequential combine across chunks ----------------
__global__ void scan_combine_kernel() {
    int idx = blockIdx.x * blockDim.x + threadIdx.x;
    if (idx >= BATCH * DI * DS) return;
    int n = idx % DS;
    int d = (idx / DS) % DI;
    int b = idx / (DS * DI);
    float h = 0.0f;
    for (int c = 0; c < NCHUNK; c++) {
        size_t base = (((size_t)b * DI + d) * NCHUNK + c) * DS + n;
        g_hin[base] = h;
        h = fmaf(g_P[base], h, g_hf[base]);
    }
}

// ---------------- 7) scan pass 2: rescan with correct h0, fused epilogue ----------------
__global__ void scan_pass2_kernel(const float* __restrict__ A_log,
                                  const float* __restrict__ Dp) {
    int d = blockIdx.x * 128 + threadIdx.x;
    int c = blockIdx.y;
    int b = blockIdx.z;
    float Aa[DS], h[DS];
    size_t hbase = (((size_t)b * DI + d) * NCHUNK + c) * DS;
    bool chain = true;
#pragma unroll
    for (int n = 0; n < DS; n++) {
        Aa[n] = -__expf(A_log[d * DS + n]);
        h[n] = g_hin[hbase + n];
    }
    float a1 = Aa[0];
#pragma unroll
    for (int n = 0; n < DS; n++)
        chain = chain && (fabsf(Aa[n] - a1 * (n + 1)) < 1e-3f * (n + 1));

    float Dd = Dp[d];
    int l0 = c * CHUNK;
    int l1 = min(LSEQ, l0 + CHUNK);
    for (int l = l0; l < l1; l++) {
        size_t row = (size_t)b * LSEQ + l;
        float dtv = g_dt[row * DI + d];
        float uv  = g_u [row * DI + d];
        float du  = dtv * uv;
        const float4* BCp = reinterpret_cast<const float4*>(&g_xdbl[row * NDBL + DTR]);
        float4 t0 = BCp[0], t1 = BCp[1], t2 = BCp[2], t3 = BCp[3];
        float4 t4 = BCp[4], t5 = BCp[5], t6 = BCp[6], t7 = BCp[7];
        float Bv[DS] = {t0.x, t0.y, t0.z, t0.w, t1.x, t1.y, t1.z, t1.w,
                        t2.x, t2.y, t2.z, t2.w, t3.x, t3.y, t3.z, t3.w};
        float Cv[DS] = {t4.x, t4.y, t4.z, t4.w, t5.x, t5.y, t5.z, t5.w,
                        t6.x, t6.y, t6.z, t6.w, t7.x, t7.y, t7.z, t7.w};
        float dA[DS];
        if (chain) {
            da_powers(__expf(dtv * a1), dA);
        } else {
#pragma unroll
            for (int n = 0; n < DS; n++) dA[n] = __expf(dtv * Aa[n]);
        }
        float y = 0.0f;
#pragma unroll
        for (int n = 0; n < DS; n++) {
            h[n] = fmaf(dA[n], h[n], du * Bv[n]);
            y = fmaf(h[n], Cv[n], y);
        }
        float z = g_xz[row * (2 * DI) + DI + d];
        g_y[row * DI + d] = (y + uv * Dd) * siluf(z);
    }
}

// ---------------- launch ----------------
extern "C" void kernel_launch(void* const* d_in, const int* in_sizes, int n_in,
                              void* d_out, int out_size) {
    const float* x          = (const float*)d_in[0];
    const float* gtok       = (const float*)d_in[1];
    const float* in_proj_w  = (const float*)d_in[2];
    const float* conv_w     = (const float*)d_in[3];
    const float* conv_b     = (const float*)d_in[4];
    const float* x_proj_w   = (const float*)d_in[5];
    const float* dt_proj_w  = (const float*)d_in[6];
    const float* dt_proj_b  = (const float*)d_in[7];
    const float* A_log      = (const float*)d_in[8];
    const float* Dp         = (const float*)d_in[9];
    const float* out_proj_w = (const float*)d_in[10];
    float* out = (float*)d_out;

    float *p_seq, *p_xz, *p_y;
    cudaGetSymbolAddress((void**)&p_seq,  g_seq);
    cudaGetSymbolAddress((void**)&p_xz,   g_xz);
    cudaGetSymbolAddress((void**)&p_y,    g_y);

    // 1. seq = [token; pixel_shuffle(x)]
    build_seq_kernel<<<(MROWS * DM + 255) / 256, 256>>>(x, gtok);

    // 2. xz = seq @ in_proj_w^T   (M=9220, N=1024, K=256)
    {
        dim3 grid((MROWS + 127) / 128, (2 * DI) / 128);
        sgemm_kernel<false><<<grid, 256>>>(p_seq, in_proj_w, p_xz, MROWS, 2 * DI, DM);
    }

    // 3. u = silu(causal_conv(xz[:, :512]) + b)
    conv_kernel<<<(MROWS * DI + 255) / 256, 256>>>(conv_w, conv_b);

    // 4+5. x_dbl = u @ x_proj_w^T, fused dt = softplus(x_dbl[:,:16] @ dt_w^T + b)
    xproj_dt_kernel<<<(MROWS + 63) / 64, 256>>>(x_proj_w, dt_proj_w, dt_proj_b);

    // 6-8. chunked selective scan + fused gating epilogue
    {
        dim3 grid(DI / 128, NCHUNK, BATCH);
        scan_pass1_kernel<<<grid, 128>>>(A_log);
        scan_combine_kernel<<<(BATCH * DI * DS + 255) / 256, 256>>>();
        scan_pass2_kernel<<<grid, 128>>>(A_log, Dp);
    }

    // 9. out = y @ out_proj_w^T, fused pixel_unshuffle write (N=256, K=512)
    {
        dim3 grid((MROWS + 127) / 128, DM / 128);
        sgemm_kernel<true><<<grid, 256>>>(p_y, out_proj_w, out, MROWS, DM, DI);
    }
}